// round 10
// baseline (speedup 1.0000x reference)
#include <cuda_runtime.h>
#include <cuda_bf16.h>

#define NN   13824
#define BB   256
#define DIM  512
#define OD   1000
#define ODP  1024
#define SK   18
#define KC   (NN / SK)             // 768
#define CUBE 24

// ---- stencil smem geometry (R9, unchanged) ----
#define H_YS 432
#define H_ZS (10 * H_YS)
#define HALO_F (4 * H_ZS)
#define WROW 676
#define WSH_F (16 * WROW)
#define STEP_SMEM ((HALO_F + WSH_F) * 4)

// ---- GEMM smem geometry: 3-stage, K=32 chunks (units = bf16) ----
#define AS_STRIDE 40               // 32 k + 8 pad; rows period-8 on banks
#define A_PLANE  (128 * AS_STRIDE) // 5120
#define B_STRIDE 136               // 128 n + 8 pad
#define B_PLANE  (32 * B_STRIDE)   // 4352
#define B_OFF    (2 * A_PLANE)     // 10240
#define STG_U    (2 * A_PLANE + 2 * B_PLANE)   // 18944 units
#define GEMM_SMEM (3 * STG_U * 2)  // 113664 B -> 2 CTA/SM

// ---------------- device scratch ----------------
__device__ float g_xp[NN * BB];
__device__ float g_h[2][NN * BB];
__device__ float g_part[SK * BB * ODP];
__device__ float g_Wp[NN * 28];
__device__ __nv_bfloat16 g_WinH[NN * DIM], g_WinL[NN * DIM];
__device__ __nv_bfloat16 g_xTH[DIM * BB],  g_xTL[DIM * BB];
__device__ __nv_bfloat16 g_WoH[OD * NN],   g_WoL[OD * NN];
__device__ __nv_bfloat16 g_hH[NN * BB],    g_hL[NN * BB];

__device__ __forceinline__ float tanh_acc(float x) {
    x = fminf(15.0f, fmaxf(-15.0f, x));
    float e = __expf(2.0f * x);
    return __fdividef(e - 1.0f, e + 1.0f);
}

// ---------------- conversions / prep ----------------
__global__ __launch_bounds__(256) void split_kernel(const float* __restrict__ s,
                                                    __nv_bfloat16* __restrict__ hi,
                                                    __nv_bfloat16* __restrict__ lo, int n4) {
    int i = blockIdx.x * 256 + threadIdx.x;
    if (i >= n4) return;
    float4 v = *(const float4*)(s + i * 4);
    __nv_bfloat16 h0 = __float2bfloat16_rn(v.x), h1 = __float2bfloat16_rn(v.y);
    __nv_bfloat16 h2 = __float2bfloat16_rn(v.z), h3 = __float2bfloat16_rn(v.w);
    __nv_bfloat162 H0 = {h0, h1}, H1 = {h2, h3};
    *(__nv_bfloat162*)(hi + i * 4) = H0;
    *(__nv_bfloat162*)(hi + i * 4 + 2) = H1;
    __nv_bfloat162 L0 = {__float2bfloat16_rn(v.x - __bfloat162float(h0)),
                         __float2bfloat16_rn(v.y - __bfloat162float(h1))};
    __nv_bfloat162 L1 = {__float2bfloat16_rn(v.z - __bfloat162float(h2)),
                         __float2bfloat16_rn(v.w - __bfloat162float(h3))};
    *(__nv_bfloat162*)(lo + i * 4) = L0;
    *(__nv_bfloat162*)(lo + i * 4 + 2) = L1;
}

__global__ __launch_bounds__(256) void split_xT_kernel(const float* __restrict__ x) {
    __shared__ float t[32][33];
    int bx = blockIdx.x * 32, kx = blockIdx.y * 32;
    int tx = threadIdx.x & 31, ty = threadIdx.x >> 5;
#pragma unroll
    for (int j = ty; j < 32; j += 8)
        t[j][tx] = x[(size_t)(bx + j) * DIM + kx + tx];
    __syncthreads();
#pragma unroll
    for (int j = ty; j < 32; j += 8) {
        float v = t[tx][j];
        __nv_bfloat16 h = __float2bfloat16_rn(v);
        size_t o = (size_t)(kx + j) * BB + bx + tx;
        g_xTH[o] = h;
        g_xTL[o] = __float2bfloat16_rn(v - __bfloat162float(h));
    }
}

__global__ __launch_bounds__(256) void wprep_kernel(const float* __restrict__ Wl) {
    int i = blockIdx.x * 256 + threadIdx.x;
    if (i >= NN * 28) return;
    int n = i / 28, k = i - n * 28;
    g_Wp[i] = (k < 27) ? Wl[n * 27 + k] : 0.f;
}

// ---------------- mma helpers ----------------
__device__ __forceinline__ void ldsm4(unsigned* r, unsigned addr) {
    asm volatile("ldmatrix.sync.aligned.m8n8.x4.shared.b16 {%0,%1,%2,%3},[%4];"
                 : "=r"(r[0]), "=r"(r[1]), "=r"(r[2]), "=r"(r[3]) : "r"(addr));
}
__device__ __forceinline__ void ldsm4t(unsigned* r, unsigned addr) {
    asm volatile("ldmatrix.sync.aligned.m8n8.x4.trans.shared.b16 {%0,%1,%2,%3},[%4];"
                 : "=r"(r[0]), "=r"(r[1]), "=r"(r[2]), "=r"(r[3]) : "r"(addr));
}
__device__ __forceinline__ void mma_bf16(float* c, const unsigned* a, const unsigned* b) {
    asm volatile("mma.sync.aligned.m16n8k16.row.col.f32.bf16.bf16.f32 "
                 "{%0,%1,%2,%3},{%4,%5,%6,%7},{%8,%9},{%0,%1,%2,%3};"
                 : "+f"(c[0]), "+f"(c[1]), "+f"(c[2]), "+f"(c[3])
                 : "r"(a[0]), "r"(a[1]), "r"(a[2]), "r"(a[3]), "r"(b[0]), "r"(b[1]));
}
__device__ __forceinline__ void cpa16(unsigned s, const void* g, int zs) {
    asm volatile("cp.async.ca.shared.global [%0],[%1],16,%2;" :: "r"(s), "l"(g), "r"(zs));
}
__device__ __forceinline__ void cpa_commit() {
    asm volatile("cp.async.commit_group;" ::: "memory");
}
__device__ __forceinline__ void cpa_wait2() {
    asm volatile("cp.async.wait_group 2;" ::: "memory");
}
__device__ __forceinline__ void cpa_wait1() {
    asm volatile("cp.async.wait_group 1;" ::: "memory");
}
__device__ __forceinline__ void cpa_wait0() {
    asm volatile("cp.async.wait_group 0;" ::: "memory");
}

// ---------------- split-precision bf16 MMA GEMM, 3-stage K32 pipeline ----------------
// MODE 0: xproj -> g_xp (+bias) AND g_h[0] = tanh(...)
// MODE 1: outgemm -> g_part
template<int MODE>
__global__ __launch_bounds__(256) void mma_gemm(
    const __nv_bfloat16* __restrict__ Ah, const __nv_bfloat16* __restrict__ Al,
    const __nv_bfloat16* __restrict__ Bh, const __nv_bfloat16* __restrict__ Bl,
    const float* __restrict__ bias, int lda, int kstages)
{
    extern __shared__ __nv_bfloat16 smem[];
    unsigned sbase = (unsigned)__cvta_generic_to_shared(smem);

    int tid = threadIdx.x;
    int m0 = blockIdx.x * 128, n0 = blockIdx.y * 128;
    int kbase = blockIdx.z * kstages * 32;
    int warp = tid >> 5, lane = tid & 31;
    int wm = warp >> 1, wn = warp & 1;

    float acc[2][8][4];
#pragma unroll
    for (int i = 0; i < 2; i++)
#pragma unroll
        for (int j = 0; j < 8; j++)
#pragma unroll
            for (int t = 0; t < 4; t++) acc[i][j][t] = 0.f;

    // staging map: A 128 rows x 4 groups(8 units) per plane -> 2 cp/thread/plane
    int ar = tid >> 1, ag0 = (tid & 1) * 2;
    // B 32 rows x 16 groups per plane -> 2 cp/thread/plane
    int br = tid >> 3, bg0 = (tid & 7) * 2;
    int okA = (MODE == 0) || (m0 + ar < OD);
    int zsA = okA ? 16 : 0;

    int lrow = ((lane >> 3) & 1) * 8 + (lane & 7);
    int lcol = (lane >> 4) * 8;

    const __nv_bfloat16* gAh0 = Ah + (size_t)(m0 + ar) * lda;
    const __nv_bfloat16* gAl0 = Al + (size_t)(m0 + ar) * lda;
    const __nv_bfloat16* gBh0 = Bh + (size_t)br * BB + n0;
    const __nv_bfloat16* gBl0 = Bl + (size_t)br * BB + n0;

    auto issue = [&](int st) {
        int kg = kbase + st * 32;
        int buf = st % 3;
        unsigned ob = sbase + 2u * (unsigned)(buf * STG_U);
#pragma unroll
        for (int j = 0; j < 2; j++) {
            int g = ag0 + j;
            unsigned sA = ob + 2u * (unsigned)(ar * AS_STRIDE + g * 8);
            cpa16(sA, gAh0 + kg + g * 8, zsA);
            cpa16(sA + 2u * A_PLANE, gAl0 + kg + g * 8, zsA);
        }
#pragma unroll
        for (int j = 0; j < 2; j++) {
            int g = bg0 + j;
            unsigned sB = ob + 2u * (unsigned)(B_OFF + br * B_STRIDE + g * 8);
            cpa16(sB, gBh0 + (size_t)kg * BB + g * 8, 16);
            cpa16(sB + 2u * B_PLANE, gBl0 + (size_t)kg * BB + g * 8, 16);
        }
        cpa_commit();
    };

    issue(0);
    issue(1);
    for (int st = 0; st < kstages; st++) {
        if (st + 2 < kstages) {
            issue(st + 2);
            cpa_wait2();
        } else if (st + 1 < kstages) {
            cpa_wait1();
        } else {
            cpa_wait0();
        }
        __syncthreads();
        unsigned ob = sbase + 2u * (unsigned)((st % 3) * STG_U);

#pragma unroll
        for (int ks = 0; ks < 2; ks++) {
            int ks16 = ks * 16;
            unsigned a_h[2][4], a_l[2][4];
#pragma unroll
            for (int mt = 0; mt < 2; mt++) {
                unsigned aaddr = ob +
                    2u * (unsigned)((wm * 32 + mt * 16 + lrow) * AS_STRIDE + ks16 + lcol);
                ldsm4(a_h[mt], aaddr);
                ldsm4(a_l[mt], aaddr + 2u * A_PLANE);
            }
#pragma unroll
            for (int np = 0; np < 4; np++) {
                unsigned b_h[4], b_l[4];
                unsigned baddr = ob +
                    2u * (unsigned)(B_OFF + (ks16 + lrow) * B_STRIDE + wn * 64 + np * 16 + lcol);
                ldsm4t(b_h, baddr);
                ldsm4t(b_l, baddr + 2u * B_PLANE);
#pragma unroll
                for (int mt = 0; mt < 2; mt++) {
                    mma_bf16(acc[mt][np * 2],     a_h[mt], b_h);
                    mma_bf16(acc[mt][np * 2],     a_l[mt], b_h);
                    mma_bf16(acc[mt][np * 2],     a_h[mt], b_l);
                    mma_bf16(acc[mt][np * 2 + 1], a_h[mt], b_h + 2);
                    mma_bf16(acc[mt][np * 2 + 1], a_l[mt], b_h + 2);
                    mma_bf16(acc[mt][np * 2 + 1], a_h[mt], b_l + 2);
                }
            }
        }
        __syncthreads();
    }

    int g = lane >> 2, ti = lane & 3;
#pragma unroll
    for (int mt = 0; mt < 2; mt++) {
#pragma unroll
        for (int nt = 0; nt < 8; nt++) {
            float* c = acc[mt][nt];
            int row = m0 + wm * 32 + mt * 16 + g;
            int col = n0 + wn * 64 + nt * 8 + 2 * ti;
            if (MODE == 0) {
                float bv0 = bias[row], bv1 = bias[row + 8];
                float v0 = c[0] + bv0, v1 = c[1] + bv0;
                float v2 = c[2] + bv1, v3 = c[3] + bv1;
                *(float2*)(g_xp + (size_t)row * BB + col) = make_float2(v0, v1);
                *(float2*)(g_xp + (size_t)(row + 8) * BB + col) = make_float2(v2, v3);
                *(float2*)(g_h[0] + (size_t)row * BB + col) =
                    make_float2(tanh_acc(v0), tanh_acc(v1));
                *(float2*)(g_h[0] + (size_t)(row + 8) * BB + col) =
                    make_float2(tanh_acc(v2), tanh_acc(v3));
            } else {
                float* base = g_part + (size_t)(blockIdx.z * BB) * ODP;
                base[(size_t)col * ODP + row] = c[0];
                base[(size_t)(col + 1) * ODP + row] = c[1];
                base[(size_t)col * ODP + row + 8] = c[2];
                base[(size_t)(col + 1) * ODP + row + 8] = c[3];
            }
        }
    }
}

// ---------------- stencil step (R9, unchanged) ----------------
#define STENCIL_X(XI, P0, P1, P2)                                              \
    {                                                                          \
        const int x = x0 + (XI);                                               \
        float wv[28];                                                          \
        _Pragma("unroll")                                                      \
        for (int t = 0; t < 7; t++)                                            \
            *(float4*)(wv + t * 4) = *(const float4*)(wq + x * 28 + t * 4);    \
        _Pragma("unroll")                                                      \
        for (int r = 0; r < 9; r++)                                            \
            P2[r] = *(const float2*)(sh + roff[r] + (x + 2) * 16);             \
        float2 s0 = accv[XI];                                                  \
        float2 s1 = make_float2(0.f, 0.f);                                     \
        float2 s2 = make_float2(0.f, 0.f);                                     \
        _Pragma("unroll")                                                      \
        for (int r = 0; r < 9; r++) {                                          \
            float w0 = wv[r * 3 + 0], w1 = wv[r * 3 + 1], w2 = wv[r * 3 + 2];  \
            s0.x = fmaf(w0, P0[r].x, s0.x); s0.y = fmaf(w0, P0[r].y, s0.y);    \
            s1.x = fmaf(w1, P1[r].x, s1.x); s1.y = fmaf(w1, P1[r].y, s1.y);    \
            s2.x = fmaf(w2, P2[r].x, s2.x); s2.y = fmaf(w2, P2[r].y, s2.y);    \
        }                                                                      \
        float2 o;                                                              \
        o.x = tanh_acc(s0.x + (s1.x + s2.x));                                  \
        o.y = tanh_acc(s0.y + (s1.y + s2.y));                                  \
        if (FINAL) {                                                           \
            __nv_bfloat16 hh0 = __float2bfloat16_rn(o.x);                      \
            __nv_bfloat16 hh1 = __float2bfloat16_rn(o.y);                      \
            __nv_bfloat162 HH = {hh0, hh1};                                    \
            __nv_bfloat162 LL = {                                              \
                __float2bfloat16_rn(o.x - __bfloat162float(hh0)),              \
                __float2bfloat16_rn(o.y - __bfloat162float(hh1))};             \
            *(__nv_bfloat162*)(hHrow + (XI) * BB) = HH;                        \
            *(__nv_bfloat162*)(hLrow + (XI) * BB) = LL;                        \
        } else {                                                               \
            *(float2*)(horow + (XI) * BB) = o;                                 \
        }                                                                      \
    }

template<int FINAL>
__global__ __launch_bounds__(256, 2) void step_kernel(int src) {
    const float* __restrict__ hin = g_h[src];
    float* __restrict__ hout = g_h[src ^ 1];

    extern __shared__ float dyn[];
    float* sh  = dyn;
    float* wsh = dyn + HALO_F;
    unsigned sb = (unsigned)__cvta_generic_to_shared(dyn);

    int tid = threadIdx.x;
    int lane = tid & 31, w = tid >> 5;
    int y0 = blockIdx.x * 8;
    int z0 = blockIdx.y * 2;
    int b0 = blockIdx.z * 16;

#pragma unroll
    for (int j = 0; j < 5; j++) {
        int row = w * 5 + j;
        int zz = row / 10, yy = row - zz * 10;
        int gz = z0 + zz - 1, gy = y0 + yy - 1;
        bool zyok = ((unsigned)gz < (unsigned)CUBE) && ((unsigned)gy < (unsigned)CUBE);
        const float* srow = hin + ((size_t)(gz * 576 + gy * 24 - 1) * BB + b0);
        unsigned drow = sb + 4u * (unsigned)(zz * H_ZS + yy * H_YS);
#pragma unroll
        for (int k = 0; k < 4; k++) {
            int f4 = lane + k * 32;
            if (f4 < 104) {
                int xx = f4 >> 2, q = f4 & 3;
                int zs = (zyok && (unsigned)(xx - 1) < (unsigned)CUBE) ? 16 : 0;
                cpa16(drow + (unsigned)(xx * 16 + q * 4) * 4u,
                      srow + (size_t)xx * BB + q * 4, zs);
            }
        }
    }
#pragma unroll
    for (int j = 0; j < 2; j++) {
        int row = w * 2 + j;
        int nr = (z0 + (row >> 3)) * 576 + (y0 + (row & 7)) * 24;
        const float* wsrc = g_Wp + (size_t)nr * 28;
        unsigned wdst = sb + 4u * (unsigned)(HALO_F + row * WROW);
#pragma unroll
        for (int k = 0; k < 6; k++) {
            int f4 = lane + k * 32;
            if (f4 < 168) cpa16(wdst + f4 * 16, wsrc + f4 * 4, 16);
        }
    }
    cpa_commit();
    cpa_wait0();
    __syncthreads();

    int q  = tid & 7;
    int ry = (tid >> 3) & 7;
    int rz = (tid >> 6) & 1;
    int xq = tid >> 7;
    int x0 = xq * 12;

    int roff[9];
#pragma unroll
    for (int dz = 0; dz < 3; dz++)
#pragma unroll
        for (int dy = 0; dy < 3; dy++)
            roff[dz * 3 + dy] = (rz + dz) * H_ZS + (ry + dy) * H_YS + q * 2;

    float2 A[9], B[9], C[9];
#pragma unroll
    for (int r = 0; r < 9; r++) {
        A[r] = *(const float2*)(sh + roff[r] + x0 * 16);
        B[r] = *(const float2*)(sh + roff[r] + (x0 + 1) * 16);
    }

    int nrow = (z0 + rz) * 576 + (y0 + ry) * 24 + x0;
    const float* wq = wsh + (rz * 8 + ry) * WROW;
    const float* xprow = g_xp + (size_t)nrow * BB + b0 + q * 2;
    float* horow = hout + (size_t)nrow * BB + b0 + q * 2;
    __nv_bfloat16* hHrow = g_hH + (size_t)nrow * BB + b0 + q * 2;
    __nv_bfloat16* hLrow = g_hL + (size_t)nrow * BB + b0 + q * 2;

    float2 accv[12];
#pragma unroll
    for (int j = 0; j < 6; j++) accv[j] = *(const float2*)(xprow + j * BB);

    STENCIL_X(0, A, B, C)
    STENCIL_X(1, B, C, A)
    STENCIL_X(2, C, A, B)

#pragma unroll
    for (int j = 6; j < 12; j++) accv[j] = *(const float2*)(xprow + j * BB);

    STENCIL_X(3, A, B, C)
    STENCIL_X(4, B, C, A)
    STENCIL_X(5, C, A, B)
    STENCIL_X(6, A, B, C)
    STENCIL_X(7, B, C, A)
    STENCIL_X(8, C, A, B)
    STENCIL_X(9, A, B, C)
    STENCIL_X(10, B, C, A)
    STENCIL_X(11, C, A, B)
}

// ---------------- reduce (float4) ----------------
__global__ __launch_bounds__(256) void reduce_kernel(const float* __restrict__ bo,
                                                     float* __restrict__ out) {
    int idx = blockIdx.x * 256 + threadIdx.x;
    if (idx >= BB * OD / 4) return;
    int b = idx / 250, o4 = idx - b * 250;
    float4 s = *(const float4*)(bo + o4 * 4);
#pragma unroll
    for (int sk = 0; sk < SK; sk++) {
        float4 p = *(const float4*)(g_part + (size_t)(sk * BB + b) * ODP + o4 * 4);
        s.x += p.x; s.y += p.y; s.z += p.z; s.w += p.w;
    }
    *(float4*)(out + (size_t)b * OD + o4 * 4) = s;
}

// ---------------- launch ----------------
extern "C" void kernel_launch(void* const* d_in, const int* in_sizes, int n_in,
                              void* d_out, int out_size) {
    const float* x   = (const float*)d_in[0];
    const float* Wi  = (const float*)d_in[1];
    const float* bi  = (const float*)d_in[2];
    const float* Wl  = (const float*)d_in[3];
    const float* Wo  = (const float*)d_in[4];
    const float* bo  = (const float*)d_in[5];
    float* out = (float*)d_out;

    cudaFuncSetAttribute(step_kernel<0>, cudaFuncAttributeMaxDynamicSharedMemorySize, STEP_SMEM);
    cudaFuncSetAttribute(step_kernel<1>, cudaFuncAttributeMaxDynamicSharedMemorySize, STEP_SMEM);
    cudaFuncSetAttribute(mma_gemm<0>, cudaFuncAttributeMaxDynamicSharedMemorySize, GEMM_SMEM);
    cudaFuncSetAttribute(mma_gemm<1>, cudaFuncAttributeMaxDynamicSharedMemorySize, GEMM_SMEM);

    __nv_bfloat16 *winH, *winL, *woH, *woL, *xtH, *xtL, *hH, *hL;
    cudaGetSymbolAddress((void**)&winH, g_WinH);
    cudaGetSymbolAddress((void**)&winL, g_WinL);
    cudaGetSymbolAddress((void**)&woH, g_WoH);
    cudaGetSymbolAddress((void**)&woL, g_WoL);
    cudaGetSymbolAddress((void**)&xtH, g_xTH);
    cudaGetSymbolAddress((void**)&xtL, g_xTL);
    cudaGetSymbolAddress((void**)&hH, g_hH);
    cudaGetSymbolAddress((void**)&hL, g_hL);

    split_kernel<<<(NN * DIM / 4 + 255) / 256, 256>>>(Wi, winH, winL, NN * DIM / 4);
    split_xT_kernel<<<dim3(BB / 32, DIM / 32), 256>>>(x);
    split_kernel<<<(OD * NN / 4 + 255) / 256, 256>>>(Wo, woH, woL, OD * NN / 4);
    wprep_kernel<<<(NN * 28 + 255) / 256, 256>>>(Wl);

    mma_gemm<0><<<dim3(NN / 128, BB / 128, 1), 256, GEMM_SMEM>>>(
        winH, winL, xtH, xtL, bi, DIM, DIM / 32);

    int src = 0;
    for (int s = 0; s < 28; s++) {
        step_kernel<0><<<dim3(CUBE / 8, CUBE / 2, BB / 16), 256, STEP_SMEM>>>(src);
        src ^= 1;
    }
    step_kernel<1><<<dim3(CUBE / 8, CUBE / 2, BB / 16), 256, STEP_SMEM>>>(src);

    mma_gemm<1><<<dim3(ODP / 128, BB / 128, SK), 256, GEMM_SMEM>>>(
        woH, woL, hH, hL, nullptr, NN, KC / 32);
    reduce_kernel<<<(BB * OD / 4 + 255) / 256, 256>>>(bo, out);
}

// round 11
// speedup vs baseline: 1.0243x; 1.0243x over previous
#include <cuda_runtime.h>
#include <cuda_bf16.h>

#define NN   13824
#define BB   256
#define DIM  512
#define OD   1000
#define ODP  1024
#define SK   9
#define KC   (NN / SK)
#define CUBE 24

// ---- stencil smem geometry (R9) ----
#define H_YS 432
#define H_ZS (10 * H_YS)
#define HALO_F (4 * H_ZS)
#define WROW 676
#define WSH_F (16 * WROW)
#define STEP_SMEM ((HALO_F + WSH_F) * 4)

// ---- GEMM smem geometry (R9: 2-stage, K64) ----
#define AS_STRIDE 72
#define BS_STRIDE 136
#define AS_PLANE  (128 * AS_STRIDE)
#define BS_PLANE  (64 * BS_STRIDE)
#define BS_OFF    (2 * AS_PLANE)
#define STG_UNITS (2 * AS_PLANE + 2 * BS_PLANE)
#define STG_BYTES (STG_UNITS * 2)
#define GEMM_SMEM (2 * STG_BYTES)

// ---------------- device scratch ----------------
__device__ float g_xp[NN * BB];
__device__ float g_h[2][NN * BB];
__device__ float g_part[SK * BB * ODP];
__device__ float g_Wp[NN * 28];
__device__ __nv_bfloat16 g_WinH[NN * DIM], g_WinL[NN * DIM];
__device__ __nv_bfloat16 g_xTH[DIM * BB],  g_xTL[DIM * BB];
__device__ __nv_bfloat16 g_WoH[OD * NN],   g_WoL[OD * NN];
__device__ __nv_bfloat16 g_hH[NN * BB],    g_hL[NN * BB];

// single-instruction MUFU.TANH
__device__ __forceinline__ float tanh_fast(float x) {
    float r;
    asm("tanh.approx.f32 %0, %1;" : "=f"(r) : "f"(x));
    return r;
}

// ---------------- conversions / prep ----------------
__global__ __launch_bounds__(256) void split_kernel(const float* __restrict__ s,
                                                    __nv_bfloat16* __restrict__ hi,
                                                    __nv_bfloat16* __restrict__ lo, int n4) {
    int i = blockIdx.x * 256 + threadIdx.x;
    if (i >= n4) return;
    float4 v = *(const float4*)(s + i * 4);
    __nv_bfloat16 h0 = __float2bfloat16_rn(v.x), h1 = __float2bfloat16_rn(v.y);
    __nv_bfloat16 h2 = __float2bfloat16_rn(v.z), h3 = __float2bfloat16_rn(v.w);
    __nv_bfloat162 H0 = {h0, h1}, H1 = {h2, h3};
    *(__nv_bfloat162*)(hi + i * 4) = H0;
    *(__nv_bfloat162*)(hi + i * 4 + 2) = H1;
    __nv_bfloat162 L0 = {__float2bfloat16_rn(v.x - __bfloat162float(h0)),
                         __float2bfloat16_rn(v.y - __bfloat162float(h1))};
    __nv_bfloat162 L1 = {__float2bfloat16_rn(v.z - __bfloat162float(h2)),
                         __float2bfloat16_rn(v.w - __bfloat162float(h3))};
    *(__nv_bfloat162*)(lo + i * 4) = L0;
    *(__nv_bfloat162*)(lo + i * 4 + 2) = L1;
}

__global__ __launch_bounds__(256) void split_xT_kernel(const float* __restrict__ x) {
    __shared__ float t[32][33];
    int bx = blockIdx.x * 32, kx = blockIdx.y * 32;
    int tx = threadIdx.x & 31, ty = threadIdx.x >> 5;
#pragma unroll
    for (int j = ty; j < 32; j += 8)
        t[j][tx] = x[(size_t)(bx + j) * DIM + kx + tx];
    __syncthreads();
#pragma unroll
    for (int j = ty; j < 32; j += 8) {
        float v = t[tx][j];
        __nv_bfloat16 h = __float2bfloat16_rn(v);
        size_t o = (size_t)(kx + j) * BB + bx + tx;
        g_xTH[o] = h;
        g_xTL[o] = __float2bfloat16_rn(v - __bfloat162float(h));
    }
}

__global__ __launch_bounds__(256) void wprep_kernel(const float* __restrict__ Wl) {
    int i = blockIdx.x * 256 + threadIdx.x;
    if (i >= NN * 28) return;
    int n = i / 28, k = i - n * 28;
    g_Wp[i] = (k < 27) ? Wl[n * 27 + k] : 0.f;
}

// ---------------- mma helpers ----------------
__device__ __forceinline__ void ldsm4(unsigned* r, unsigned addr) {
    asm volatile("ldmatrix.sync.aligned.m8n8.x4.shared.b16 {%0,%1,%2,%3},[%4];"
                 : "=r"(r[0]), "=r"(r[1]), "=r"(r[2]), "=r"(r[3]) : "r"(addr));
}
__device__ __forceinline__ void ldsm4t(unsigned* r, unsigned addr) {
    asm volatile("ldmatrix.sync.aligned.m8n8.x4.trans.shared.b16 {%0,%1,%2,%3},[%4];"
                 : "=r"(r[0]), "=r"(r[1]), "=r"(r[2]), "=r"(r[3]) : "r"(addr));
}
__device__ __forceinline__ void mma_bf16(float* c, const unsigned* a, const unsigned* b) {
    asm volatile("mma.sync.aligned.m16n8k16.row.col.f32.bf16.bf16.f32 "
                 "{%0,%1,%2,%3},{%4,%5,%6,%7},{%8,%9},{%0,%1,%2,%3};"
                 : "+f"(c[0]), "+f"(c[1]), "+f"(c[2]), "+f"(c[3])
                 : "r"(a[0]), "r"(a[1]), "r"(a[2]), "r"(a[3]), "r"(b[0]), "r"(b[1]));
}
__device__ __forceinline__ void cpa16(unsigned s, const void* g, int zs) {
    asm volatile("cp.async.ca.shared.global [%0],[%1],16,%2;" :: "r"(s), "l"(g), "r"(zs));
}
__device__ __forceinline__ void cpa_commit() {
    asm volatile("cp.async.commit_group;" ::: "memory");
}
__device__ __forceinline__ void cpa_wait1() {
    asm volatile("cp.async.wait_group 1;" ::: "memory");
}
__device__ __forceinline__ void cpa_wait0() {
    asm volatile("cp.async.wait_group 0;" ::: "memory");
}

// ---------------- split-precision bf16 MMA GEMM (R9 config) ----------------
template<int MODE>
__global__ __launch_bounds__(256) void mma_gemm(
    const __nv_bfloat16* __restrict__ Ah, const __nv_bfloat16* __restrict__ Al,
    const __nv_bfloat16* __restrict__ Bh, const __nv_bfloat16* __restrict__ Bl,
    const float* __restrict__ bias, int lda, int kstages)
{
    extern __shared__ __nv_bfloat16 smem[];
    unsigned sbase = (unsigned)__cvta_generic_to_shared(smem);

    int tid = threadIdx.x;
    int m0 = blockIdx.x * 128, n0 = blockIdx.y * 128;
    int kbase = blockIdx.z * kstages * 64;
    int warp = tid >> 5, lane = tid & 31;
    int wm = warp >> 1, wn = warp & 1;

    float acc[2][8][4];
#pragma unroll
    for (int i = 0; i < 2; i++)
#pragma unroll
        for (int j = 0; j < 8; j++)
#pragma unroll
            for (int t = 0; t < 4; t++) acc[i][j][t] = 0.f;

    int ar = tid >> 1, acu = (tid & 1) * 4;
    int br = tid >> 2, bcu = (tid & 3) * 4;
    int okA = (MODE == 0) || (m0 + ar < OD);
    int zsA = okA ? 16 : 0;
    unsigned sA0 = sbase + 2u * (unsigned)(ar * AS_STRIDE + acu * 8);
    unsigned sB0 = sbase + 2u * (unsigned)(BS_OFF + br * BS_STRIDE + bcu * 8);

    int lrow = ((lane >> 3) & 1) * 8 + (lane & 7);
    int lcol = (lane >> 4) * 8;

    const __nv_bfloat16* gAh0 = Ah + (size_t)(m0 + ar) * lda + acu * 8;
    const __nv_bfloat16* gAl0 = Al + (size_t)(m0 + ar) * lda + acu * 8;
    const __nv_bfloat16* gBh0 = Bh + (size_t)br * BB + n0 + bcu * 8;
    const __nv_bfloat16* gBl0 = Bl + (size_t)br * BB + n0 + bcu * 8;

    auto issue = [&](int st) {
        int kg = kbase + st * 64;
        unsigned off = (st & 1) * (unsigned)STG_BYTES;
        const __nv_bfloat16* gAh = gAh0 + kg;
        const __nv_bfloat16* gAl = gAl0 + kg;
        const __nv_bfloat16* gBh = gBh0 + (size_t)kg * BB;
        const __nv_bfloat16* gBl = gBl0 + (size_t)kg * BB;
#pragma unroll
        for (int j = 0; j < 4; j++) {
            cpa16(sA0 + off + j * 16, gAh + j * 8, zsA);
            cpa16(sA0 + off + 2 * AS_PLANE + j * 16, gAl + j * 8, zsA);
            cpa16(sB0 + off + j * 16, gBh + j * 8, 16);
            cpa16(sB0 + off + 2 * BS_PLANE + j * 16, gBl + j * 8, 16);
        }
        cpa_commit();
    };

    issue(0);
    for (int st = 0; st < kstages; st++) {
        if (st + 1 < kstages) issue(st + 1);
        if (st + 1 < kstages) cpa_wait1(); else cpa_wait0();
        __syncthreads();
        unsigned off = (st & 1) * (unsigned)STG_BYTES;

#pragma unroll
        for (int ks = 0; ks < 4; ks++) {
            int ks16 = ks * 16;
            unsigned a_h[2][4], a_l[2][4];
#pragma unroll
            for (int mt = 0; mt < 2; mt++) {
                unsigned aaddr = sbase + off +
                    2u * (unsigned)((wm * 32 + mt * 16 + lrow) * AS_STRIDE + ks16 + lcol);
                ldsm4(a_h[mt], aaddr);
                ldsm4(a_l[mt], aaddr + 2 * AS_PLANE);
            }
#pragma unroll
            for (int np = 0; np < 4; np++) {
                unsigned b_h[4], b_l[4];
                unsigned baddr = sbase + off +
                    2u * (unsigned)(BS_OFF + (ks16 + lrow) * BS_STRIDE + wn * 64 + np * 16 + lcol);
                ldsm4t(b_h, baddr);
                ldsm4t(b_l, baddr + 2 * BS_PLANE);
#pragma unroll
                for (int mt = 0; mt < 2; mt++) {
                    mma_bf16(acc[mt][np * 2],     a_h[mt], b_h);
                    mma_bf16(acc[mt][np * 2],     a_l[mt], b_h);
                    mma_bf16(acc[mt][np * 2],     a_h[mt], b_l);
                    mma_bf16(acc[mt][np * 2 + 1], a_h[mt], b_h + 2);
                    mma_bf16(acc[mt][np * 2 + 1], a_l[mt], b_h + 2);
                    mma_bf16(acc[mt][np * 2 + 1], a_h[mt], b_l + 2);
                }
            }
        }
        __syncthreads();
    }

    int g = lane >> 2, ti = lane & 3;
#pragma unroll
    for (int mt = 0; mt < 2; mt++) {
#pragma unroll
        for (int nt = 0; nt < 8; nt++) {
            float* c = acc[mt][nt];
            int row = m0 + wm * 32 + mt * 16 + g;
            int col = n0 + wn * 64 + nt * 8 + 2 * ti;
            if (MODE == 0) {
                float bv0 = bias[row], bv1 = bias[row + 8];
                float v0 = c[0] + bv0, v1 = c[1] + bv0;
                float v2 = c[2] + bv1, v3 = c[3] + bv1;
                *(float2*)(g_xp + (size_t)row * BB + col) = make_float2(v0, v1);
                *(float2*)(g_xp + (size_t)(row + 8) * BB + col) = make_float2(v2, v3);
                *(float2*)(g_h[0] + (size_t)row * BB + col) =
                    make_float2(tanh_fast(v0), tanh_fast(v1));
                *(float2*)(g_h[0] + (size_t)(row + 8) * BB + col) =
                    make_float2(tanh_fast(v2), tanh_fast(v3));
            } else {
                float* base = g_part + (size_t)(blockIdx.z * BB) * ODP;
                base[(size_t)col * ODP + row] = c[0];
                base[(size_t)(col + 1) * ODP + row] = c[1];
                base[(size_t)col * ODP + row + 8] = c[2];
                base[(size_t)(col + 1) * ODP + row + 8] = c[3];
            }
        }
    }
}

// ---------------- stencil step (R9 core, MUFU.TANH) ----------------
#define STENCIL_X(XI, P0, P1, P2)                                              \
    {                                                                          \
        const int x = x0 + (XI);                                               \
        float wv[28];                                                          \
        _Pragma("unroll")                                                      \
        for (int t = 0; t < 7; t++)                                            \
            *(float4*)(wv + t * 4) = *(const float4*)(wq + x * 28 + t * 4);    \
        _Pragma("unroll")                                                      \
        for (int r = 0; r < 9; r++)                                            \
            P2[r] = *(const float2*)(sh + roff[r] + (x + 2) * 16);             \
        float2 s0 = accv[XI];                                                  \
        float2 s1 = make_float2(0.f, 0.f);                                     \
        float2 s2 = make_float2(0.f, 0.f);                                     \
        _Pragma("unroll")                                                      \
        for (int r = 0; r < 9; r++) {                                          \
            float w0 = wv[r * 3 + 0], w1 = wv[r * 3 + 1], w2 = wv[r * 3 + 2];  \
            s0.x = fmaf(w0, P0[r].x, s0.x); s0.y = fmaf(w0, P0[r].y, s0.y);    \
            s1.x = fmaf(w1, P1[r].x, s1.x); s1.y = fmaf(w1, P1[r].y, s1.y);    \
            s2.x = fmaf(w2, P2[r].x, s2.x); s2.y = fmaf(w2, P2[r].y, s2.y);    \
        }                                                                      \
        float2 o;                                                              \
        o.x = tanh_fast(s0.x + (s1.x + s2.x));                                 \
        o.y = tanh_fast(s0.y + (s1.y + s2.y));                                 \
        if (FINAL) {                                                           \
            __nv_bfloat16 hh0 = __float2bfloat16_rn(o.x);                      \
            __nv_bfloat16 hh1 = __float2bfloat16_rn(o.y);                      \
            __nv_bfloat162 HH = {hh0, hh1};                                    \
            __nv_bfloat162 LL = {                                              \
                __float2bfloat16_rn(o.x - __bfloat162float(hh0)),              \
                __float2bfloat16_rn(o.y - __bfloat162float(hh1))};             \
            *(__nv_bfloat162*)(hHrow + (XI) * BB) = HH;                        \
            *(__nv_bfloat162*)(hLrow + (XI) * BB) = LL;                        \
        } else {                                                               \
            *(float2*)(horow + (XI) * BB) = o;                                 \
        }                                                                      \
    }

template<int FINAL>
__global__ __launch_bounds__(256, 2) void step_kernel(int src) {
    const float* __restrict__ hin = g_h[src];
    float* __restrict__ hout = g_h[src ^ 1];

    extern __shared__ float dyn[];
    float* sh  = dyn;
    float* wsh = dyn + HALO_F;
    unsigned sb = (unsigned)__cvta_generic_to_shared(dyn);

    int tid = threadIdx.x;
    int lane = tid & 31, w = tid >> 5;
    int y0 = blockIdx.x * 8;
    int z0 = blockIdx.y * 2;
    int b0 = blockIdx.z * 16;

#pragma unroll
    for (int j = 0; j < 5; j++) {
        int row = w * 5 + j;
        int zz = row / 10, yy = row - zz * 10;
        int gz = z0 + zz - 1, gy = y0 + yy - 1;
        bool zyok = ((unsigned)gz < (unsigned)CUBE) && ((unsigned)gy < (unsigned)CUBE);
        const float* srow = hin + ((size_t)(gz * 576 + gy * 24 - 1) * BB + b0);
        unsigned drow = sb + 4u * (unsigned)(zz * H_ZS + yy * H_YS);
#pragma unroll
        for (int k = 0; k < 4; k++) {
            int f4 = lane + k * 32;
            if (f4 < 104) {
                int xx = f4 >> 2, q = f4 & 3;
                int zs = (zyok && (unsigned)(xx - 1) < (unsigned)CUBE) ? 16 : 0;
                cpa16(drow + (unsigned)(xx * 16 + q * 4) * 4u,
                      srow + (size_t)xx * BB + q * 4, zs);
            }
        }
    }
#pragma unroll
    for (int j = 0; j < 2; j++) {
        int row = w * 2 + j;
        int nr = (z0 + (row >> 3)) * 576 + (y0 + (row & 7)) * 24;
        const float* wsrc = g_Wp + (size_t)nr * 28;
        unsigned wdst = sb + 4u * (unsigned)(HALO_F + row * WROW);
#pragma unroll
        for (int k = 0; k < 6; k++) {
            int f4 = lane + k * 32;
            if (f4 < 168) cpa16(wdst + f4 * 16, wsrc + f4 * 4, 16);
        }
    }
    cpa_commit();
    cpa_wait0();
    __syncthreads();

    int q  = tid & 7;
    int ry = (tid >> 3) & 7;
    int rz = (tid >> 6) & 1;
    int xq = tid >> 7;
    int x0 = xq * 12;

    int roff[9];
#pragma unroll
    for (int dz = 0; dz < 3; dz++)
#pragma unroll
        for (int dy = 0; dy < 3; dy++)
            roff[dz * 3 + dy] = (rz + dz) * H_ZS + (ry + dy) * H_YS + q * 2;

    float2 A[9], B[9], C[9];
#pragma unroll
    for (int r = 0; r < 9; r++) {
        A[r] = *(const float2*)(sh + roff[r] + x0 * 16);
        B[r] = *(const float2*)(sh + roff[r] + (x0 + 1) * 16);
    }

    int nrow = (z0 + rz) * 576 + (y0 + ry) * 24 + x0;
    const float* wq = wsh + (rz * 8 + ry) * WROW;
    const float* xprow = g_xp + (size_t)nrow * BB + b0 + q * 2;
    float* horow = hout + (size_t)nrow * BB + b0 + q * 2;
    __nv_bfloat16* hHrow = g_hH + (size_t)nrow * BB + b0 + q * 2;
    __nv_bfloat16* hLrow = g_hL + (size_t)nrow * BB + b0 + q * 2;

    float2 accv[12];
#pragma unroll
    for (int j = 0; j < 6; j++) accv[j] = *(const float2*)(xprow + j * BB);

    STENCIL_X(0, A, B, C)
    STENCIL_X(1, B, C, A)
    STENCIL_X(2, C, A, B)

#pragma unroll
    for (int j = 6; j < 12; j++) accv[j] = *(const float2*)(xprow + j * BB);

    STENCIL_X(3, A, B, C)
    STENCIL_X(4, B, C, A)
    STENCIL_X(5, C, A, B)
    STENCIL_X(6, A, B, C)
    STENCIL_X(7, B, C, A)
    STENCIL_X(8, C, A, B)
    STENCIL_X(9, A, B, C)
    STENCIL_X(10, B, C, A)
    STENCIL_X(11, C, A, B)
}

// ---------------- reduce (float4) ----------------
__global__ __launch_bounds__(256) void reduce_kernel(const float* __restrict__ bo,
                                                     float* __restrict__ out) {
    int idx = blockIdx.x * 256 + threadIdx.x;
    if (idx >= BB * OD / 4) return;
    int b = idx / 250, o4 = idx - b * 250;
    float4 s = *(const float4*)(bo + o4 * 4);
#pragma unroll
    for (int sk = 0; sk < SK; sk++) {
        float4 p = *(const float4*)(g_part + (size_t)(sk * BB + b) * ODP + o4 * 4);
        s.x += p.x; s.y += p.y; s.z += p.z; s.w += p.w;
    }
    *(float4*)(out + (size_t)b * OD + o4 * 4) = s;
}

// ---------------- launch ----------------
extern "C" void kernel_launch(void* const* d_in, const int* in_sizes, int n_in,
                              void* d_out, int out_size) {
    const float* x   = (const float*)d_in[0];
    const float* Wi  = (const float*)d_in[1];
    const float* bi  = (const float*)d_in[2];
    const float* Wl  = (const float*)d_in[3];
    const float* Wo  = (const float*)d_in[4];
    const float* bo  = (const float*)d_in[5];
    float* out = (float*)d_out;

    cudaFuncSetAttribute(step_kernel<0>, cudaFuncAttributeMaxDynamicSharedMemorySize, STEP_SMEM);
    cudaFuncSetAttribute(step_kernel<1>, cudaFuncAttributeMaxDynamicSharedMemorySize, STEP_SMEM);
    cudaFuncSetAttribute(mma_gemm<0>, cudaFuncAttributeMaxDynamicSharedMemorySize, GEMM_SMEM);
    cudaFuncSetAttribute(mma_gemm<1>, cudaFuncAttributeMaxDynamicSharedMemorySize, GEMM_SMEM);

    __nv_bfloat16 *winH, *winL, *woH, *woL, *xtH, *xtL, *hH, *hL;
    cudaGetSymbolAddress((void**)&winH, g_WinH);
    cudaGetSymbolAddress((void**)&winL, g_WinL);
    cudaGetSymbolAddress((void**)&woH, g_WoH);
    cudaGetSymbolAddress((void**)&woL, g_WoL);
    cudaGetSymbolAddress((void**)&xtH, g_xTH);
    cudaGetSymbolAddress((void**)&xtL, g_xTL);
    cudaGetSymbolAddress((void**)&hH, g_hH);
    cudaGetSymbolAddress((void**)&hL, g_hL);

    split_kernel<<<(NN * DIM / 4 + 255) / 256, 256>>>(Wi, winH, winL, NN * DIM / 4);
    split_xT_kernel<<<dim3(BB / 32, DIM / 32), 256>>>(x);
    split_kernel<<<(OD * NN / 4 + 255) / 256, 256>>>(Wo, woH, woL, OD * NN / 4);
    wprep_kernel<<<(NN * 28 + 255) / 256, 256>>>(Wl);

    mma_gemm<0><<<dim3(NN / 128, BB / 128, 1), 256, GEMM_SMEM>>>(
        winH, winL, xtH, xtL, bi, DIM, DIM / 64);

    int src = 0;
    for (int s = 0; s < 28; s++) {
        step_kernel<0><<<dim3(CUBE / 8, CUBE / 2, BB / 16), 256, STEP_SMEM>>>(src);
        src ^= 1;
    }
    step_kernel<1><<<dim3(CUBE / 8, CUBE / 2, BB / 16), 256, STEP_SMEM>>>(src);

    mma_gemm<1><<<dim3(ODP / 128, BB / 128, SK), 256, GEMM_SMEM>>>(
        woH, woL, hH, hL, nullptr, NN, KC / 64);
    reduce_kernel<<<(BB * OD / 4 + 255) / 256, 256>>>(bo, out);
}

// round 12
// speedup vs baseline: 1.0483x; 1.0234x over previous
#include <cuda_runtime.h>
#include <cuda_bf16.h>

#define NN   13824
#define BB   256
#define DIM  512
#define OD   1000
#define ODP  1024
#define SK   9
#define KC   (NN / SK)
#define CUBE 24
#define NBLK 288
#define NSTEPS 29

// ---- stencil smem geometry (R9) ----
#define H_YS 432
#define H_ZS (10 * H_YS)
#define HALO_F (4 * H_ZS)
#define WROW 676
#define WSH_F (16 * WROW)
#define STEP_SMEM ((HALO_F + WSH_F) * 4)   // 112384 B -> 2 CTA/SM

// ---- GEMM smem geometry (R9: 2-stage, K64) ----
#define AS_STRIDE 72
#define BS_STRIDE 136
#define AS_PLANE  (128 * AS_STRIDE)
#define BS_PLANE  (64 * BS_STRIDE)
#define BS_OFF    (2 * AS_PLANE)
#define STG_UNITS (2 * AS_PLANE + 2 * BS_PLANE)
#define STG_BYTES (STG_UNITS * 2)
#define GEMM_SMEM (2 * STG_BYTES)

// ---------------- device scratch ----------------
__device__ float g_xp[NN * BB];
__device__ float g_h[2][NN * BB];
__device__ float g_part[SK * BB * ODP];
__device__ float g_Wp[NN * 28];
__device__ __nv_bfloat16 g_WinH[NN * DIM], g_WinL[NN * DIM];
__device__ __nv_bfloat16 g_xTH[DIM * BB],  g_xTL[DIM * BB];
__device__ __nv_bfloat16 g_WoH[OD * NN],   g_WoL[OD * NN];
__device__ __nv_bfloat16 g_hH[NN * BB],    g_hL[NN * BB];
__device__ unsigned g_bar_arrive;   // zero-init; returns to 0 every barrier
__device__ unsigned g_bar_gen;      // monotonic across graph replays

__device__ __forceinline__ float tanh_fast(float x) {
    float r;
    asm("tanh.approx.f32 %0, %1;" : "=f"(r) : "f"(x));
    return r;
}

// ---------------- conversions / prep ----------------
__global__ __launch_bounds__(256) void split_kernel(const float* __restrict__ s,
                                                    __nv_bfloat16* __restrict__ hi,
                                                    __nv_bfloat16* __restrict__ lo, int n4) {
    int i = blockIdx.x * 256 + threadIdx.x;
    if (i >= n4) return;
    float4 v = *(const float4*)(s + i * 4);
    __nv_bfloat16 h0 = __float2bfloat16_rn(v.x), h1 = __float2bfloat16_rn(v.y);
    __nv_bfloat16 h2 = __float2bfloat16_rn(v.z), h3 = __float2bfloat16_rn(v.w);
    __nv_bfloat162 H0 = {h0, h1}, H1 = {h2, h3};
    *(__nv_bfloat162*)(hi + i * 4) = H0;
    *(__nv_bfloat162*)(hi + i * 4 + 2) = H1;
    __nv_bfloat162 L0 = {__float2bfloat16_rn(v.x - __bfloat162float(h0)),
                         __float2bfloat16_rn(v.y - __bfloat162float(h1))};
    __nv_bfloat162 L1 = {__float2bfloat16_rn(v.z - __bfloat162float(h2)),
                         __float2bfloat16_rn(v.w - __bfloat162float(h3))};
    *(__nv_bfloat162*)(lo + i * 4) = L0;
    *(__nv_bfloat162*)(lo + i * 4 + 2) = L1;
}

__global__ __launch_bounds__(256) void split_xT_kernel(const float* __restrict__ x) {
    __shared__ float t[32][33];
    int bx = blockIdx.x * 32, kx = blockIdx.y * 32;
    int tx = threadIdx.x & 31, ty = threadIdx.x >> 5;
#pragma unroll
    for (int j = ty; j < 32; j += 8)
        t[j][tx] = x[(size_t)(bx + j) * DIM + kx + tx];
    __syncthreads();
#pragma unroll
    for (int j = ty; j < 32; j += 8) {
        float v = t[tx][j];
        __nv_bfloat16 h = __float2bfloat16_rn(v);
        size_t o = (size_t)(kx + j) * BB + bx + tx;
        g_xTH[o] = h;
        g_xTL[o] = __float2bfloat16_rn(v - __bfloat162float(h));
    }
}

__global__ __launch_bounds__(256) void wprep_kernel(const float* __restrict__ Wl) {
    int i = blockIdx.x * 256 + threadIdx.x;
    if (i >= NN * 28) return;
    int n = i / 28, k = i - n * 28;
    g_Wp[i] = (k < 27) ? Wl[n * 27 + k] : 0.f;
}

// ---------------- mma helpers ----------------
__device__ __forceinline__ void ldsm4(unsigned* r, unsigned addr) {
    asm volatile("ldmatrix.sync.aligned.m8n8.x4.shared.b16 {%0,%1,%2,%3},[%4];"
                 : "=r"(r[0]), "=r"(r[1]), "=r"(r[2]), "=r"(r[3]) : "r"(addr));
}
__device__ __forceinline__ void ldsm4t(unsigned* r, unsigned addr) {
    asm volatile("ldmatrix.sync.aligned.m8n8.x4.trans.shared.b16 {%0,%1,%2,%3},[%4];"
                 : "=r"(r[0]), "=r"(r[1]), "=r"(r[2]), "=r"(r[3]) : "r"(addr));
}
__device__ __forceinline__ void mma_bf16(float* c, const unsigned* a, const unsigned* b) {
    asm volatile("mma.sync.aligned.m16n8k16.row.col.f32.bf16.bf16.f32 "
                 "{%0,%1,%2,%3},{%4,%5,%6,%7},{%8,%9},{%0,%1,%2,%3};"
                 : "+f"(c[0]), "+f"(c[1]), "+f"(c[2]), "+f"(c[3])
                 : "r"(a[0]), "r"(a[1]), "r"(a[2]), "r"(a[3]), "r"(b[0]), "r"(b[1]));
}
__device__ __forceinline__ void cpa16(unsigned s, const void* g, int zs) {
    asm volatile("cp.async.ca.shared.global [%0],[%1],16,%2;" :: "r"(s), "l"(g), "r"(zs));
}
__device__ __forceinline__ void cpa_commit() {
    asm volatile("cp.async.commit_group;" ::: "memory");
}
__device__ __forceinline__ void cpa_wait1() {
    asm volatile("cp.async.wait_group 1;" ::: "memory");
}
__device__ __forceinline__ void cpa_wait0() {
    asm volatile("cp.async.wait_group 0;" ::: "memory");
}

// ---------------- split-precision bf16 MMA GEMM (R9 config) ----------------
template<int MODE>
__global__ __launch_bounds__(256) void mma_gemm(
    const __nv_bfloat16* __restrict__ Ah, const __nv_bfloat16* __restrict__ Al,
    const __nv_bfloat16* __restrict__ Bh, const __nv_bfloat16* __restrict__ Bl,
    const float* __restrict__ bias, int lda, int kstages)
{
    extern __shared__ __nv_bfloat16 smem[];
    unsigned sbase = (unsigned)__cvta_generic_to_shared(smem);

    int tid = threadIdx.x;
    int m0 = blockIdx.x * 128, n0 = blockIdx.y * 128;
    int kbase = blockIdx.z * kstages * 64;
    int warp = tid >> 5, lane = tid & 31;
    int wm = warp >> 1, wn = warp & 1;

    float acc[2][8][4];
#pragma unroll
    for (int i = 0; i < 2; i++)
#pragma unroll
        for (int j = 0; j < 8; j++)
#pragma unroll
            for (int t = 0; t < 4; t++) acc[i][j][t] = 0.f;

    int ar = tid >> 1, acu = (tid & 1) * 4;
    int br = tid >> 2, bcu = (tid & 3) * 4;
    int okA = (MODE == 0) || (m0 + ar < OD);
    int zsA = okA ? 16 : 0;
    unsigned sA0 = sbase + 2u * (unsigned)(ar * AS_STRIDE + acu * 8);
    unsigned sB0 = sbase + 2u * (unsigned)(BS_OFF + br * BS_STRIDE + bcu * 8);

    int lrow = ((lane >> 3) & 1) * 8 + (lane & 7);
    int lcol = (lane >> 4) * 8;

    const __nv_bfloat16* gAh0 = Ah + (size_t)(m0 + ar) * lda + acu * 8;
    const __nv_bfloat16* gAl0 = Al + (size_t)(m0 + ar) * lda + acu * 8;
    const __nv_bfloat16* gBh0 = Bh + (size_t)br * BB + n0 + bcu * 8;
    const __nv_bfloat16* gBl0 = Bl + (size_t)br * BB + n0 + bcu * 8;

    auto issue = [&](int st) {
        int kg = kbase + st * 64;
        unsigned off = (st & 1) * (unsigned)STG_BYTES;
        const __nv_bfloat16* gAh = gAh0 + kg;
        const __nv_bfloat16* gAl = gAl0 + kg;
        const __nv_bfloat16* gBh = gBh0 + (size_t)kg * BB;
        const __nv_bfloat16* gBl = gBl0 + (size_t)kg * BB;
#pragma unroll
        for (int j = 0; j < 4; j++) {
            cpa16(sA0 + off + j * 16, gAh + j * 8, zsA);
            cpa16(sA0 + off + 2 * AS_PLANE + j * 16, gAl + j * 8, zsA);
            cpa16(sB0 + off + j * 16, gBh + j * 8, 16);
            cpa16(sB0 + off + 2 * BS_PLANE + j * 16, gBl + j * 8, 16);
        }
        cpa_commit();
    };

    issue(0);
    for (int st = 0; st < kstages; st++) {
        if (st + 1 < kstages) issue(st + 1);
        if (st + 1 < kstages) cpa_wait1(); else cpa_wait0();
        __syncthreads();
        unsigned off = (st & 1) * (unsigned)STG_BYTES;

#pragma unroll
        for (int ks = 0; ks < 4; ks++) {
            int ks16 = ks * 16;
            unsigned a_h[2][4], a_l[2][4];
#pragma unroll
            for (int mt = 0; mt < 2; mt++) {
                unsigned aaddr = sbase + off +
                    2u * (unsigned)((wm * 32 + mt * 16 + lrow) * AS_STRIDE + ks16 + lcol);
                ldsm4(a_h[mt], aaddr);
                ldsm4(a_l[mt], aaddr + 2 * AS_PLANE);
            }
#pragma unroll
            for (int np = 0; np < 4; np++) {
                unsigned b_h[4], b_l[4];
                unsigned baddr = sbase + off +
                    2u * (unsigned)(BS_OFF + (ks16 + lrow) * BS_STRIDE + wn * 64 + np * 16 + lcol);
                ldsm4t(b_h, baddr);
                ldsm4t(b_l, baddr + 2 * BS_PLANE);
#pragma unroll
                for (int mt = 0; mt < 2; mt++) {
                    mma_bf16(acc[mt][np * 2],     a_h[mt], b_h);
                    mma_bf16(acc[mt][np * 2],     a_l[mt], b_h);
                    mma_bf16(acc[mt][np * 2],     a_h[mt], b_l);
                    mma_bf16(acc[mt][np * 2 + 1], a_h[mt], b_h + 2);
                    mma_bf16(acc[mt][np * 2 + 1], a_l[mt], b_h + 2);
                    mma_bf16(acc[mt][np * 2 + 1], a_h[mt], b_l + 2);
                }
            }
        }
        __syncthreads();
    }

    int g = lane >> 2, ti = lane & 3;
#pragma unroll
    for (int mt = 0; mt < 2; mt++) {
#pragma unroll
        for (int nt = 0; nt < 8; nt++) {
            float* c = acc[mt][nt];
            int row = m0 + wm * 32 + mt * 16 + g;
            int col = n0 + wn * 64 + nt * 8 + 2 * ti;
            if (MODE == 0) {
                float bv0 = bias[row], bv1 = bias[row + 8];
                float v0 = c[0] + bv0, v1 = c[1] + bv0;
                float v2 = c[2] + bv1, v3 = c[3] + bv1;
                *(float2*)(g_xp + (size_t)row * BB + col) = make_float2(v0, v1);
                *(float2*)(g_xp + (size_t)(row + 8) * BB + col) = make_float2(v2, v3);
                *(float2*)(g_h[0] + (size_t)row * BB + col) =
                    make_float2(tanh_fast(v0), tanh_fast(v1));
                *(float2*)(g_h[0] + (size_t)(row + 8) * BB + col) =
                    make_float2(tanh_fast(v2), tanh_fast(v3));
            } else {
                float* base = g_part + (size_t)(blockIdx.z * BB) * ODP;
                base[(size_t)col * ODP + row] = c[0];
                base[(size_t)(col + 1) * ODP + row] = c[1];
                base[(size_t)col * ODP + row + 8] = c[2];
                base[(size_t)(col + 1) * ODP + row + 8] = c[3];
            }
        }
    }
}

// ---------------- persistent stencil kernel: all 29 steps in one launch ----------------
#define STENCIL_X(XI, P0, P1, P2)                                              \
    {                                                                          \
        const int x = x0 + (XI);                                               \
        float wv[28];                                                          \
        _Pragma("unroll")                                                      \
        for (int t = 0; t < 7; t++)                                            \
            *(float4*)(wv + t * 4) = *(const float4*)(wq + x * 28 + t * 4);    \
        _Pragma("unroll")                                                      \
        for (int r = 0; r < 9; r++)                                            \
            P2[r] = *(const float2*)(sh + roff[r] + (x + 2) * 16);             \
        float2 s0 = accv[XI];                                                  \
        float2 s1 = make_float2(0.f, 0.f);                                     \
        float2 s2 = make_float2(0.f, 0.f);                                     \
        _Pragma("unroll")                                                      \
        for (int r = 0; r < 9; r++) {                                          \
            float w0 = wv[r * 3 + 0], w1 = wv[r * 3 + 1], w2 = wv[r * 3 + 2];  \
            s0.x = fmaf(w0, P0[r].x, s0.x); s0.y = fmaf(w0, P0[r].y, s0.y);    \
            s1.x = fmaf(w1, P1[r].x, s1.x); s1.y = fmaf(w1, P1[r].y, s1.y);    \
            s2.x = fmaf(w2, P2[r].x, s2.x); s2.y = fmaf(w2, P2[r].y, s2.y);    \
        }                                                                      \
        float2 o;                                                              \
        o.x = tanh_fast(s0.x + (s1.x + s2.x));                                 \
        o.y = tanh_fast(s0.y + (s1.y + s2.y));                                 \
        if (fin) {                                                             \
            __nv_bfloat16 hh0 = __float2bfloat16_rn(o.x);                      \
            __nv_bfloat16 hh1 = __float2bfloat16_rn(o.y);                      \
            __nv_bfloat162 HH = {hh0, hh1};                                    \
            __nv_bfloat162 LL = {                                              \
                __float2bfloat16_rn(o.x - __bfloat162float(hh0)),              \
                __float2bfloat16_rn(o.y - __bfloat162float(hh1))};             \
            *(__nv_bfloat162*)(hHrow + (XI) * BB) = HH;                        \
            *(__nv_bfloat162*)(hLrow + (XI) * BB) = LL;                        \
        } else {                                                               \
            *(float2*)(horow + (XI) * BB) = o;                                 \
        }                                                                      \
    }

__global__ __launch_bounds__(256, 2) void steps_persist() {
    extern __shared__ float dyn[];
    float* sh  = dyn;
    float* wsh = dyn + HALO_F;
    unsigned sb = (unsigned)__cvta_generic_to_shared(dyn);

    int tid = threadIdx.x;
    int lane = tid & 31, w = tid >> 5;
    int bq = blockIdx.x & 7;          // batch quarter (pass adds 8)
    int zy = blockIdx.x >> 3;         // 36 (y,z) tiles
    int y0 = (zy % 3) * 8;
    int z0 = (zy / 3) * 2;

    unsigned start_gen = 0;
    if (tid == 0) start_gen = *(volatile unsigned*)&g_bar_gen;

    // ---- weights staged ONCE for all 29 steps ----
#pragma unroll
    for (int j = 0; j < 2; j++) {
        int row = w * 2 + j;
        int nr = (z0 + (row >> 3)) * 576 + (y0 + (row & 7)) * 24;
        const float* wsrc = g_Wp + (size_t)nr * 28;
        unsigned wdst = sb + 4u * (unsigned)(HALO_F + row * WROW);
#pragma unroll
        for (int k = 0; k < 6; k++) {
            int f4 = lane + k * 32;
            if (f4 < 168) cpa16(wdst + f4 * 16, wsrc + f4 * 4, 16);
        }
    }
    cpa_commit();

    // compute-thread mapping (constant across steps)
    int q  = tid & 7;
    int ry = (tid >> 3) & 7;
    int rz = (tid >> 6) & 1;
    int xq = tid >> 7;
    int x0 = xq * 12;

    int roff[9];
#pragma unroll
    for (int dz = 0; dz < 3; dz++)
#pragma unroll
        for (int dy = 0; dy < 3; dy++)
            roff[dz * 3 + dy] = (rz + dz) * H_ZS + (ry + dy) * H_YS + q * 2;

    const float* wq = wsh + (rz * 8 + ry) * WROW;
    int nrow = (z0 + rz) * 576 + (y0 + ry) * 24 + x0;

    int src = 0;
    for (int step = 0; step < NSTEPS; step++) {
        const bool fin = (step == NSTEPS - 1);
        const float* __restrict__ hin = g_h[src];
        float* __restrict__ hout = g_h[src ^ 1];

        for (int pass = 0; pass < 2; pass++) {
            int b0 = (bq + pass * 8) * 16;
            __syncthreads();   // halo buffer free (prev pass/step consumed)

            // halo staging (cp.async zfill)
#pragma unroll
            for (int j = 0; j < 5; j++) {
                int row = w * 5 + j;
                int zz = row / 10, yy = row - zz * 10;
                int gz = z0 + zz - 1, gy = y0 + yy - 1;
                bool zyok = ((unsigned)gz < (unsigned)CUBE) && ((unsigned)gy < (unsigned)CUBE);
                const float* srow = hin + ((size_t)(gz * 576 + gy * 24 - 1) * BB + b0);
                unsigned drow = sb + 4u * (unsigned)(zz * H_ZS + yy * H_YS);
#pragma unroll
                for (int k = 0; k < 4; k++) {
                    int f4 = lane + k * 32;
                    if (f4 < 104) {
                        int xx = f4 >> 2, qq = f4 & 3;
                        int zs = (zyok && (unsigned)(xx - 1) < (unsigned)CUBE) ? 16 : 0;
                        cpa16(drow + (unsigned)(xx * 16 + qq * 4) * 4u,
                              srow + (size_t)xx * BB + qq * 4, zs);
                    }
                }
            }
            cpa_commit();
            cpa_wait0();
            __syncthreads();

            const float* xprow = g_xp + (size_t)nrow * BB + b0 + q * 2;
            float* horow = hout + (size_t)nrow * BB + b0 + q * 2;
            __nv_bfloat16* hHrow = g_hH + (size_t)nrow * BB + b0 + q * 2;
            __nv_bfloat16* hLrow = g_hL + (size_t)nrow * BB + b0 + q * 2;

            float2 A[9], B[9], C[9];
#pragma unroll
            for (int r = 0; r < 9; r++) {
                A[r] = *(const float2*)(sh + roff[r] + x0 * 16);
                B[r] = *(const float2*)(sh + roff[r] + (x0 + 1) * 16);
            }
            float2 accv[12];
#pragma unroll
            for (int j = 0; j < 6; j++) accv[j] = *(const float2*)(xprow + j * BB);

            STENCIL_X(0, A, B, C)
            STENCIL_X(1, B, C, A)
            STENCIL_X(2, C, A, B)
#pragma unroll
            for (int j = 6; j < 12; j++) accv[j] = *(const float2*)(xprow + j * BB);
            STENCIL_X(3, A, B, C)
            STENCIL_X(4, B, C, A)
            STENCIL_X(5, C, A, B)
            STENCIL_X(6, A, B, C)
            STENCIL_X(7, B, C, A)
            STENCIL_X(8, C, A, B)
            STENCIL_X(9, A, B, C)
            STENCIL_X(10, B, C, A)
            STENCIL_X(11, C, A, B)
        }

        // ---- grid barrier (release/acquire) ----
        __syncthreads();
        if (tid == 0) {
            __threadfence();
            unsigned old = atomicAdd(&g_bar_arrive, 1u);
            unsigned target = start_gen + (unsigned)step + 1u;
            if (old == (unsigned)(NBLK - 1)) {
                g_bar_arrive = 0u;
                __threadfence();
                atomicAdd(&g_bar_gen, 1u);
            } else {
                while ((int)(*(volatile unsigned*)&g_bar_gen - target) < 0)
                    __nanosleep(64);
            }
            __threadfence();
        }
        __syncthreads();
        src ^= 1;
    }
}

// ---------------- reduce (float4) ----------------
__global__ __launch_bounds__(256) void reduce_kernel(const float* __restrict__ bo,
                                                     float* __restrict__ out) {
    int idx = blockIdx.x * 256 + threadIdx.x;
    if (idx >= BB * OD / 4) return;
    int b = idx / 250, o4 = idx - b * 250;
    float4 s = *(const float4*)(bo + o4 * 4);
#pragma unroll
    for (int sk = 0; sk < SK; sk++) {
        float4 p = *(const float4*)(g_part + (size_t)(sk * BB + b) * ODP + o4 * 4);
        s.x += p.x; s.y += p.y; s.z += p.z; s.w += p.w;
    }
    *(float4*)(out + (size_t)b * OD + o4 * 4) = s;
}

// ---------------- launch ----------------
extern "C" void kernel_launch(void* const* d_in, const int* in_sizes, int n_in,
                              void* d_out, int out_size) {
    const float* x   = (const float*)d_in[0];
    const float* Wi  = (const float*)d_in[1];
    const float* bi  = (const float*)d_in[2];
    const float* Wl  = (const float*)d_in[3];
    const float* Wo  = (const float*)d_in[4];
    const float* bo  = (const float*)d_in[5];
    float* out = (float*)d_out;

    cudaFuncSetAttribute(steps_persist, cudaFuncAttributeMaxDynamicSharedMemorySize, STEP_SMEM);
    cudaFuncSetAttribute(mma_gemm<0>, cudaFuncAttributeMaxDynamicSharedMemorySize, GEMM_SMEM);
    cudaFuncSetAttribute(mma_gemm<1>, cudaFuncAttributeMaxDynamicSharedMemorySize, GEMM_SMEM);

    __nv_bfloat16 *winH, *winL, *woH, *woL, *xtH, *xtL, *hH, *hL;
    cudaGetSymbolAddress((void**)&winH, g_WinH);
    cudaGetSymbolAddress((void**)&winL, g_WinL);
    cudaGetSymbolAddress((void**)&woH, g_WoH);
    cudaGetSymbolAddress((void**)&woL, g_WoL);
    cudaGetSymbolAddress((void**)&xtH, g_xTH);
    cudaGetSymbolAddress((void**)&xtL, g_xTL);
    cudaGetSymbolAddress((void**)&hH, g_hH);
    cudaGetSymbolAddress((void**)&hL, g_hL);

    split_kernel<<<(NN * DIM / 4 + 255) / 256, 256>>>(Wi, winH, winL, NN * DIM / 4);
    split_xT_kernel<<<dim3(BB / 32, DIM / 32), 256>>>(x);
    split_kernel<<<(OD * NN / 4 + 255) / 256, 256>>>(Wo, woH, woL, OD * NN / 4);
    wprep_kernel<<<(NN * 28 + 255) / 256, 256>>>(Wl);

    mma_gemm<0><<<dim3(NN / 128, BB / 128, 1), 256, GEMM_SMEM>>>(
        winH, winL, xtH, xtL, bi, DIM, DIM / 64);

    steps_persist<<<NBLK, 256, STEP_SMEM>>>();

    mma_gemm<1><<<dim3(ODP / 128, BB / 128, SK), 256, GEMM_SMEM>>>(
        woH, woL, hH, hL, nullptr, NN, KC / 64);
    reduce_kernel<<<(BB * OD / 4 + 255) / 256, 256>>>(bo, out);
}

// round 13
// speedup vs baseline: 1.0834x; 1.0335x over previous
#include <cuda_runtime.h>
#include <cuda_bf16.h>

#define NN   13824
#define BB   256
#define DIM  512
#define OD   1000
#define ODP  1024
#define SK   9
#define KC   (NN / SK)
#define CUBE 24
#define NBLK 144
#define NSTEPS 29

// ---- stencil smem geometry: DOUBLE-buffered halo + weights ----
#define H_YS 432
#define H_ZS (10 * H_YS)
#define HALO_F (4 * H_ZS)                    // 17280 floats per buffer
#define WROW 676
#define WSH_F (16 * WROW)                    // 10816
#define STEP_SMEM ((2 * HALO_F + WSH_F) * 4) // 181504 B -> 1 CTA/SM

// ---- GEMM smem geometry (R9: 2-stage, K64) ----
#define AS_STRIDE 72
#define BS_STRIDE 136
#define AS_PLANE  (128 * AS_STRIDE)
#define BS_PLANE  (64 * BS_STRIDE)
#define BS_OFF    (2 * AS_PLANE)
#define STG_UNITS (2 * AS_PLANE + 2 * BS_PLANE)
#define STG_BYTES (STG_UNITS * 2)
#define GEMM_SMEM (2 * STG_BYTES)

// ---------------- device scratch ----------------
__device__ float g_xp[NN * BB];
__device__ float g_h[2][NN * BB];
__device__ float g_part[SK * BB * ODP];
__device__ float g_Wp[NN * 28];
__device__ __nv_bfloat16 g_WinH[NN * DIM], g_WinL[NN * DIM];
__device__ __nv_bfloat16 g_xTH[DIM * BB],  g_xTL[DIM * BB];
__device__ __nv_bfloat16 g_WoH[OD * NN],   g_WoL[OD * NN];
__device__ __nv_bfloat16 g_hH[NN * BB],    g_hL[NN * BB];
__device__ unsigned g_bar_arrive;
__device__ unsigned g_bar_gen;

__device__ __forceinline__ float tanh_fast(float x) {
    float r;
    asm("tanh.approx.f32 %0, %1;" : "=f"(r) : "f"(x));
    return r;
}

// ---------------- conversions / prep ----------------
__global__ __launch_bounds__(256) void split_kernel(const float* __restrict__ s,
                                                    __nv_bfloat16* __restrict__ hi,
                                                    __nv_bfloat16* __restrict__ lo, int n4) {
    int i = blockIdx.x * 256 + threadIdx.x;
    if (i >= n4) return;
    float4 v = *(const float4*)(s + i * 4);
    __nv_bfloat16 h0 = __float2bfloat16_rn(v.x), h1 = __float2bfloat16_rn(v.y);
    __nv_bfloat16 h2 = __float2bfloat16_rn(v.z), h3 = __float2bfloat16_rn(v.w);
    __nv_bfloat162 H0 = {h0, h1}, H1 = {h2, h3};
    *(__nv_bfloat162*)(hi + i * 4) = H0;
    *(__nv_bfloat162*)(hi + i * 4 + 2) = H1;
    __nv_bfloat162 L0 = {__float2bfloat16_rn(v.x - __bfloat162float(h0)),
                         __float2bfloat16_rn(v.y - __bfloat162float(h1))};
    __nv_bfloat162 L1 = {__float2bfloat16_rn(v.z - __bfloat162float(h2)),
                         __float2bfloat16_rn(v.w - __bfloat162float(h3))};
    *(__nv_bfloat162*)(lo + i * 4) = L0;
    *(__nv_bfloat162*)(lo + i * 4 + 2) = L1;
}

__global__ __launch_bounds__(256) void split_xT_kernel(const float* __restrict__ x) {
    __shared__ float t[32][33];
    int bx = blockIdx.x * 32, kx = blockIdx.y * 32;
    int tx = threadIdx.x & 31, ty = threadIdx.x >> 5;
#pragma unroll
    for (int j = ty; j < 32; j += 8)
        t[j][tx] = x[(size_t)(bx + j) * DIM + kx + tx];
    __syncthreads();
#pragma unroll
    for (int j = ty; j < 32; j += 8) {
        float v = t[tx][j];
        __nv_bfloat16 h = __float2bfloat16_rn(v);
        size_t o = (size_t)(kx + j) * BB + bx + tx;
        g_xTH[o] = h;
        g_xTL[o] = __float2bfloat16_rn(v - __bfloat162float(h));
    }
}

__global__ __launch_bounds__(256) void wprep_kernel(const float* __restrict__ Wl) {
    int i = blockIdx.x * 256 + threadIdx.x;
    if (i >= NN * 28) return;
    int n = i / 28, k = i - n * 28;
    g_Wp[i] = (k < 27) ? Wl[n * 27 + k] : 0.f;
}

// ---------------- mma helpers ----------------
__device__ __forceinline__ void ldsm4(unsigned* r, unsigned addr) {
    asm volatile("ldmatrix.sync.aligned.m8n8.x4.shared.b16 {%0,%1,%2,%3},[%4];"
                 : "=r"(r[0]), "=r"(r[1]), "=r"(r[2]), "=r"(r[3]) : "r"(addr));
}
__device__ __forceinline__ void ldsm4t(unsigned* r, unsigned addr) {
    asm volatile("ldmatrix.sync.aligned.m8n8.x4.trans.shared.b16 {%0,%1,%2,%3},[%4];"
                 : "=r"(r[0]), "=r"(r[1]), "=r"(r[2]), "=r"(r[3]) : "r"(addr));
}
__device__ __forceinline__ void mma_bf16(float* c, const unsigned* a, const unsigned* b) {
    asm volatile("mma.sync.aligned.m16n8k16.row.col.f32.bf16.bf16.f32 "
                 "{%0,%1,%2,%3},{%4,%5,%6,%7},{%8,%9},{%0,%1,%2,%3};"
                 : "+f"(c[0]), "+f"(c[1]), "+f"(c[2]), "+f"(c[3])
                 : "r"(a[0]), "r"(a[1]), "r"(a[2]), "r"(a[3]), "r"(b[0]), "r"(b[1]));
}
__device__ __forceinline__ void cpa16(unsigned s, const void* g, int zs) {
    asm volatile("cp.async.ca.shared.global [%0],[%1],16,%2;" :: "r"(s), "l"(g), "r"(zs));
}
__device__ __forceinline__ void cpa_commit() {
    asm volatile("cp.async.commit_group;" ::: "memory");
}
__device__ __forceinline__ void cpa_wait1() {
    asm volatile("cp.async.wait_group 1;" ::: "memory");
}
__device__ __forceinline__ void cpa_wait0() {
    asm volatile("cp.async.wait_group 0;" ::: "memory");
}

// ---------------- split-precision bf16 MMA GEMM (R9 config) ----------------
template<int MODE>
__global__ __launch_bounds__(256) void mma_gemm(
    const __nv_bfloat16* __restrict__ Ah, const __nv_bfloat16* __restrict__ Al,
    const __nv_bfloat16* __restrict__ Bh, const __nv_bfloat16* __restrict__ Bl,
    const float* __restrict__ bias, int lda, int kstages)
{
    extern __shared__ __nv_bfloat16 smem[];
    unsigned sbase = (unsigned)__cvta_generic_to_shared(smem);

    int tid = threadIdx.x;
    int m0 = blockIdx.x * 128, n0 = blockIdx.y * 128;
    int kbase = blockIdx.z * kstages * 64;
    int warp = tid >> 5, lane = tid & 31;
    int wm = warp >> 1, wn = warp & 1;

    float acc[2][8][4];
#pragma unroll
    for (int i = 0; i < 2; i++)
#pragma unroll
        for (int j = 0; j < 8; j++)
#pragma unroll
            for (int t = 0; t < 4; t++) acc[i][j][t] = 0.f;

    int ar = tid >> 1, acu = (tid & 1) * 4;
    int br = tid >> 2, bcu = (tid & 3) * 4;
    int okA = (MODE == 0) || (m0 + ar < OD);
    int zsA = okA ? 16 : 0;
    unsigned sA0 = sbase + 2u * (unsigned)(ar * AS_STRIDE + acu * 8);
    unsigned sB0 = sbase + 2u * (unsigned)(BS_OFF + br * BS_STRIDE + bcu * 8);

    int lrow = ((lane >> 3) & 1) * 8 + (lane & 7);
    int lcol = (lane >> 4) * 8;

    const __nv_bfloat16* gAh0 = Ah + (size_t)(m0 + ar) * lda + acu * 8;
    const __nv_bfloat16* gAl0 = Al + (size_t)(m0 + ar) * lda + acu * 8;
    const __nv_bfloat16* gBh0 = Bh + (size_t)br * BB + n0 + bcu * 8;
    const __nv_bfloat16* gBl0 = Bl + (size_t)br * BB + n0 + bcu * 8;

    auto issue = [&](int st) {
        int kg = kbase + st * 64;
        unsigned off = (st & 1) * (unsigned)STG_BYTES;
        const __nv_bfloat16* gAh = gAh0 + kg;
        const __nv_bfloat16* gAl = gAl0 + kg;
        const __nv_bfloat16* gBh = gBh0 + (size_t)kg * BB;
        const __nv_bfloat16* gBl = gBl0 + (size_t)kg * BB;
#pragma unroll
        for (int j = 0; j < 4; j++) {
            cpa16(sA0 + off + j * 16, gAh + j * 8, zsA);
            cpa16(sA0 + off + 2 * AS_PLANE + j * 16, gAl + j * 8, zsA);
            cpa16(sB0 + off + j * 16, gBh + j * 8, 16);
            cpa16(sB0 + off + 2 * BS_PLANE + j * 16, gBl + j * 8, 16);
        }
        cpa_commit();
    };

    issue(0);
    for (int st = 0; st < kstages; st++) {
        if (st + 1 < kstages) issue(st + 1);
        if (st + 1 < kstages) cpa_wait1(); else cpa_wait0();
        __syncthreads();
        unsigned off = (st & 1) * (unsigned)STG_BYTES;

#pragma unroll
        for (int ks = 0; ks < 4; ks++) {
            int ks16 = ks * 16;
            unsigned a_h[2][4], a_l[2][4];
#pragma unroll
            for (int mt = 0; mt < 2; mt++) {
                unsigned aaddr = sbase + off +
                    2u * (unsigned)((wm * 32 + mt * 16 + lrow) * AS_STRIDE + ks16 + lcol);
                ldsm4(a_h[mt], aaddr);
                ldsm4(a_l[mt], aaddr + 2 * AS_PLANE);
            }
#pragma unroll
            for (int np = 0; np < 4; np++) {
                unsigned b_h[4], b_l[4];
                unsigned baddr = sbase + off +
                    2u * (unsigned)(BS_OFF + (ks16 + lrow) * BS_STRIDE + wn * 64 + np * 16 + lcol);
                ldsm4t(b_h, baddr);
                ldsm4t(b_l, baddr + 2 * BS_PLANE);
#pragma unroll
                for (int mt = 0; mt < 2; mt++) {
                    mma_bf16(acc[mt][np * 2],     a_h[mt], b_h);
                    mma_bf16(acc[mt][np * 2],     a_l[mt], b_h);
                    mma_bf16(acc[mt][np * 2],     a_h[mt], b_l);
                    mma_bf16(acc[mt][np * 2 + 1], a_h[mt], b_h + 2);
                    mma_bf16(acc[mt][np * 2 + 1], a_l[mt], b_h + 2);
                    mma_bf16(acc[mt][np * 2 + 1], a_h[mt], b_l + 2);
                }
            }
        }
        __syncthreads();
    }

    int g = lane >> 2, ti = lane & 3;
#pragma unroll
    for (int mt = 0; mt < 2; mt++) {
#pragma unroll
        for (int nt = 0; nt < 8; nt++) {
            float* c = acc[mt][nt];
            int row = m0 + wm * 32 + mt * 16 + g;
            int col = n0 + wn * 64 + nt * 8 + 2 * ti;
            if (MODE == 0) {
                float bv0 = bias[row], bv1 = bias[row + 8];
                float v0 = c[0] + bv0, v1 = c[1] + bv0;
                float v2 = c[2] + bv1, v3 = c[3] + bv1;
                *(float2*)(g_xp + (size_t)row * BB + col) = make_float2(v0, v1);
                *(float2*)(g_xp + (size_t)(row + 8) * BB + col) = make_float2(v2, v3);
                *(float2*)(g_h[0] + (size_t)row * BB + col) =
                    make_float2(tanh_fast(v0), tanh_fast(v1));
                *(float2*)(g_h[0] + (size_t)(row + 8) * BB + col) =
                    make_float2(tanh_fast(v2), tanh_fast(v3));
            } else {
                float* base = g_part + (size_t)(blockIdx.z * BB) * ODP;
                base[(size_t)col * ODP + row] = c[0];
                base[(size_t)(col + 1) * ODP + row] = c[1];
                base[(size_t)col * ODP + row + 8] = c[2];
                base[(size_t)(col + 1) * ODP + row + 8] = c[3];
            }
        }
    }
}

// ---------------- persistent stencil: pipelined halo staging ----------------
#define STENCIL_X(XI, P0, P1, P2)                                              \
    {                                                                          \
        const int x = x0 + (XI);                                               \
        float wv[28];                                                          \
        _Pragma("unroll")                                                      \
        for (int t = 0; t < 7; t++)                                            \
            *(float4*)(wv + t * 4) = *(const float4*)(wq + x * 28 + t * 4);    \
        _Pragma("unroll")                                                      \
        for (int r = 0; r < 9; r++)                                            \
            P2[r] = *(const float2*)(sh + roff[r] + (x + 2) * 16);             \
        float2 s0 = accv[XI];                                                  \
        float2 s1 = make_float2(0.f, 0.f);                                     \
        float2 s2 = make_float2(0.f, 0.f);                                     \
        _Pragma("unroll")                                                      \
        for (int r = 0; r < 9; r++) {                                          \
            float w0 = wv[r * 3 + 0], w1 = wv[r * 3 + 1], w2 = wv[r * 3 + 2];  \
            s0.x = fmaf(w0, P0[r].x, s0.x); s0.y = fmaf(w0, P0[r].y, s0.y);    \
            s1.x = fmaf(w1, P1[r].x, s1.x); s1.y = fmaf(w1, P1[r].y, s1.y);    \
            s2.x = fmaf(w2, P2[r].x, s2.x); s2.y = fmaf(w2, P2[r].y, s2.y);    \
        }                                                                      \
        float2 o;                                                              \
        o.x = tanh_fast(s0.x + (s1.x + s2.x));                                 \
        o.y = tanh_fast(s0.y + (s1.y + s2.y));                                 \
        if (fin) {                                                             \
            __nv_bfloat16 hh0 = __float2bfloat16_rn(o.x);                      \
            __nv_bfloat16 hh1 = __float2bfloat16_rn(o.y);                      \
            __nv_bfloat162 HH = {hh0, hh1};                                    \
            __nv_bfloat162 LL = {                                              \
                __float2bfloat16_rn(o.x - __bfloat162float(hh0)),              \
                __float2bfloat16_rn(o.y - __bfloat162float(hh1))};             \
            *(__nv_bfloat162*)(hHrow + (XI) * BB) = HH;                        \
            *(__nv_bfloat162*)(hLrow + (XI) * BB) = LL;                        \
        } else {                                                               \
            *(float2*)(horow + (XI) * BB) = o;                                 \
        }                                                                      \
    }

__global__ __launch_bounds__(256, 1) void steps_persist() {
    extern __shared__ float dyn[];
    float* wsh = dyn + 2 * HALO_F;
    unsigned sb = (unsigned)__cvta_generic_to_shared(dyn);

    int tid = threadIdx.x;
    int lane = tid & 31, w = tid >> 5;
    int bq = blockIdx.x & 3;          // batch quarter owner: passes p -> b0=(bq*4+p)*16
    int zy = blockIdx.x >> 2;         // 36 zy tiles
    int y0 = (zy % 3) * 8;
    int z0 = (zy / 3) * 2;

    unsigned start_gen = 0;
    if (tid == 0) start_gen = *(volatile unsigned*)&g_bar_gen;

    // weights staged ONCE
#pragma unroll
    for (int j = 0; j < 2; j++) {
        int row = w * 2 + j;
        int nr = (z0 + (row >> 3)) * 576 + (y0 + (row & 7)) * 24;
        const float* wsrc = g_Wp + (size_t)nr * 28;
        unsigned wdst = sb + 4u * (unsigned)(2 * HALO_F + row * WROW);
#pragma unroll
        for (int k = 0; k < 6; k++) {
            int f4 = lane + k * 32;
            if (f4 < 168) cpa16(wdst + f4 * 16, wsrc + f4 * 4, 16);
        }
    }
    cpa_commit();
    cpa_wait0();

    int q  = tid & 7;
    int ry = (tid >> 3) & 7;
    int rz = (tid >> 6) & 1;
    int xq = tid >> 7;
    int x0 = xq * 12;

    int roff[9];
#pragma unroll
    for (int dz = 0; dz < 3; dz++)
#pragma unroll
        for (int dy = 0; dy < 3; dy++)
            roff[dz * 3 + dy] = (rz + dz) * H_ZS + (ry + dy) * H_YS + q * 2;

    const float* wq = wsh + (rz * 8 + ry) * WROW;
    int nrow = (z0 + rz) * 576 + (y0 + ry) * 24 + x0;

    int src = 0;
    for (int step = 0; step < NSTEPS; step++) {
        const bool fin = (step == NSTEPS - 1);
        const float* __restrict__ hin = g_h[src];
        float* __restrict__ hout = g_h[src ^ 1];

        // staging helper: pass p into buffer p&1
        auto stage = [&](int p) {
            int b0 = (bq * 4 + p) * 16;
            unsigned bufo = (unsigned)((p & 1) * HALO_F);
#pragma unroll
            for (int j = 0; j < 5; j++) {
                int row = w * 5 + j;
                int zz = row / 10, yy = row - zz * 10;
                int gz = z0 + zz - 1, gy = y0 + yy - 1;
                bool zyok = ((unsigned)gz < (unsigned)CUBE) && ((unsigned)gy < (unsigned)CUBE);
                const float* srow = hin + ((size_t)(gz * 576 + gy * 24 - 1) * BB + b0);
                unsigned drow = sb + 4u * (bufo + (unsigned)(zz * H_ZS + yy * H_YS));
#pragma unroll
                for (int k = 0; k < 4; k++) {
                    int f4 = lane + k * 32;
                    if (f4 < 104) {
                        int xx = f4 >> 2, qq = f4 & 3;
                        int zs = (zyok && (unsigned)(xx - 1) < (unsigned)CUBE) ? 16 : 0;
                        cpa16(drow + (unsigned)(xx * 16 + qq * 4) * 4u,
                              srow + (size_t)xx * BB + qq * 4, zs);
                    }
                }
            }
            cpa_commit();
        };

        stage(0);
        for (int p = 0; p < 4; p++) {
            if (p < 3) { stage(p + 1); cpa_wait1(); }
            else       { cpa_wait0(); }
            __syncthreads();

            const float* sh = dyn + (p & 1) * HALO_F;
            int b0 = (bq * 4 + p) * 16;
            const float* xprow = g_xp + (size_t)nrow * BB + b0 + q * 2;
            float* horow = hout + (size_t)nrow * BB + b0 + q * 2;
            __nv_bfloat16* hHrow = g_hH + (size_t)nrow * BB + b0 + q * 2;
            __nv_bfloat16* hLrow = g_hL + (size_t)nrow * BB + b0 + q * 2;

            float2 A[9], B[9], C[9];
#pragma unroll
            for (int r = 0; r < 9; r++) {
                A[r] = *(const float2*)(sh + roff[r] + x0 * 16);
                B[r] = *(const float2*)(sh + roff[r] + (x0 + 1) * 16);
            }
            float2 accv[12];
#pragma unroll
            for (int j = 0; j < 6; j++) accv[j] = *(const float2*)(xprow + j * BB);

            STENCIL_X(0, A, B, C)
            STENCIL_X(1, B, C, A)
            STENCIL_X(2, C, A, B)
#pragma unroll
            for (int j = 6; j < 12; j++) accv[j] = *(const float2*)(xprow + j * BB);
            STENCIL_X(3, A, B, C)
            STENCIL_X(4, B, C, A)
            STENCIL_X(5, C, A, B)
            STENCIL_X(6, A, B, C)
            STENCIL_X(7, B, C, A)
            STENCIL_X(8, C, A, B)
            STENCIL_X(9, A, B, C)
            STENCIL_X(10, B, C, A)
            STENCIL_X(11, C, A, B)
            __syncthreads();
        }

        // grid barrier
        if (tid == 0) {
            __threadfence();
            unsigned old = atomicAdd(&g_bar_arrive, 1u);
            unsigned target = start_gen + (unsigned)step + 1u;
            if (old == (unsigned)(NBLK - 1)) {
                g_bar_arrive = 0u;
                __threadfence();
                atomicAdd(&g_bar_gen, 1u);
            } else {
                while ((int)(*(volatile unsigned*)&g_bar_gen - target) < 0)
                    __nanosleep(32);
            }
            __threadfence();
        }
        __syncthreads();
        src ^= 1;
    }
}

// ---------------- reduce (float4) ----------------
__global__ __launch_bounds__(256) void reduce_kernel(const float* __restrict__ bo,
                                                     float* __restrict__ out) {
    int idx = blockIdx.x * 256 + threadIdx.x;
    if (idx >= BB * OD / 4) return;
    int b = idx / 250, o4 = idx - b * 250;
    float4 s = *(const float4*)(bo + o4 * 4);
#pragma unroll
    for (int sk = 0; sk < SK; sk++) {
        float4 p = *(const float4*)(g_part + (size_t)(sk * BB + b) * ODP + o4 * 4);
        s.x += p.x; s.y += p.y; s.z += p.z; s.w += p.w;
    }
    *(float4*)(out + (size_t)b * OD + o4 * 4) = s;
}

// ---------------- launch ----------------
extern "C" void kernel_launch(void* const* d_in, const int* in_sizes, int n_in,
                              void* d_out, int out_size) {
    const float* x   = (const float*)d_in[0];
    const float* Wi  = (const float*)d_in[1];
    const float* bi  = (const float*)d_in[2];
    const float* Wl  = (const float*)d_in[3];
    const float* Wo  = (const float*)d_in[4];
    const float* bo  = (const float*)d_in[5];
    float* out = (float*)d_out;

    cudaFuncSetAttribute(steps_persist, cudaFuncAttributeMaxDynamicSharedMemorySize, STEP_SMEM);
    cudaFuncSetAttribute(mma_gemm<0>, cudaFuncAttributeMaxDynamicSharedMemorySize, GEMM_SMEM);
    cudaFuncSetAttribute(mma_gemm<1>, cudaFuncAttributeMaxDynamicSharedMemorySize, GEMM_SMEM);

    __nv_bfloat16 *winH, *winL, *woH, *woL, *xtH, *xtL, *hH, *hL;
    cudaGetSymbolAddress((void**)&winH, g_WinH);
    cudaGetSymbolAddress((void**)&winL, g_WinL);
    cudaGetSymbolAddress((void**)&woH, g_WoH);
    cudaGetSymbolAddress((void**)&woL, g_WoL);
    cudaGetSymbolAddress((void**)&xtH, g_xTH);
    cudaGetSymbolAddress((void**)&xtL, g_xTL);
    cudaGetSymbolAddress((void**)&hH, g_hH);
    cudaGetSymbolAddress((void**)&hL, g_hL);

    split_kernel<<<(NN * DIM / 4 + 255) / 256, 256>>>(Wi, winH, winL, NN * DIM / 4);
    split_xT_kernel<<<dim3(BB / 32, DIM / 32), 256>>>(x);
    split_kernel<<<(OD * NN / 4 + 255) / 256, 256>>>(Wo, woH, woL, OD * NN / 4);
    wprep_kernel<<<(NN * 28 + 255) / 256, 256>>>(Wl);

    mma_gemm<0><<<dim3(NN / 128, BB / 128, 1), 256, GEMM_SMEM>>>(
        winH, winL, xtH, xtL, bi, DIM, DIM / 64);

    steps_persist<<<NBLK, 256, STEP_SMEM>>>();

    mma_gemm<1><<<dim3(ODP / 128, BB / 128, SK), 256, GEMM_SMEM>>>(
        woH, woL, hH, hL, nullptr, NN, KC / 64);
    reduce_kernel<<<(BB * OD / 4 + 255) / 256, 256>>>(bo, out);
}